// round 16
// baseline (speedup 1.0000x reference)
#include <cuda_runtime.h>
#include <stdint.h>

#define BATCH 4096
#define IN_F  2048
#define OUT_F 4096
#define WORDS (IN_F / 64)     // 32 u64 per row
#define HT_SIZE 16384
#define HT_MASK (HT_SIZE - 1)
#define KCAP  8               // per-batch-row candidate cap (expected use: 0)

// Scratch (allocation-free: __device__ globals; zero-init at load, and k2
// returns HT/counters to zero every run -> graph replays deterministic).
__device__ uint64_t g_xbits[(size_t)BATCH * WORDS];
__device__ uint64_t g_pbits[(size_t)OUT_F * WORDS];
__device__ uint32_t g_xsig[BATCH];
__device__ uint32_t g_psig[OUT_F];
__device__ unsigned long long g_ht[HT_SIZE];  // [63:32] sig32, bit31 marker, bit30 type, [29:0] row
__device__ uint32_t g_cnt[BATCH];
__device__ uint32_t g_olist[BATCH][KCAP];

// -----------------------------------------------------------------------------
// Kernel 1: fused pack + zero-fill + insert-time match detection.
//   1024 blocks x 256 threads. Each block packs 8 rows (one warp per row) AND
//   zero-fills a 4096-float4 slice of the output (proven 128 MB mixed stream).
//   Pack: float4 loads, 4 ballots/iter — fixed bit permutation identical for
//   x and path rows, so packed-row equality <=> original-bit-row equality.
//   Lane 0 of each warp CAS-inserts (sig32|type|row) into a global linear-probe
//   HT. Linear-probe invariant: the later-resting of any two same-sig entries
//   always inspects the earlier's immutable slot via its failed CAS -> every
//   cross-type sig-equal pair is detected exactly once. Candidates are only
//   RECORDED here (no verify -> hot loop stays lean); k2 verifies exactly.
// -----------------------------------------------------------------------------
__global__ __launch_bounds__(256) void fsu_pack_zero_kernel(
    const float* __restrict__ x,
    const float* __restrict__ w,
    const float* __restrict__ rng,
    float4* __restrict__ outv)
{
    // ---- zero-fill slice (pure store stream, overlaps pack loads) ----
    {
        const float4 z = make_float4(0.0f, 0.0f, 0.0f, 0.0f);
        const int base = blockIdx.x * 4096;          // 4M float4 / 1024 blocks
        #pragma unroll
        for (int k = 0; k < 16; ++k)
            outv[base + k * 256 + threadIdx.x] = z;
    }

    // ---- pack 8 rows (one warp per row) ----
    const int gwarp = (blockIdx.x * blockDim.x + threadIdx.x) >> 5;
    const int lane  = threadIdx.x & 31;
    const bool isX  = gwarp < BATCH;
    const int row   = isX ? gwarp : (gwarp - BATCH);

    const float rv = __ldg(rng);
    const float4* src = reinterpret_cast<const float4*>(
        (isX ? (x + (size_t)row * IN_F) : (w + (size_t)row * IN_F)));

    uint64_t sig = 0;
    uint64_t myword = 0;

    #pragma unroll
    for (int it = 0; it < IN_F / 128; ++it) {        // 16 iterations
        const float4 v = __ldg(src + it * 32 + lane);
        bool b0, b1, b2, b3;
        if (isX) {
            b0 = (v.x > 0.5f); b1 = (v.y > 0.5f);
            b2 = (v.z > 0.5f); b3 = (v.w > 0.5f);
        } else {
            // BinGen/BSGen: prob=(w+1)*0.5; source=round(prob*256); bit = source > rng
            b0 = (rintf((v.x + 1.0f) * 0.5f * 256.0f) > rv);
            b1 = (rintf((v.y + 1.0f) * 0.5f * 256.0f) > rv);
            b2 = (rintf((v.z + 1.0f) * 0.5f * 256.0f) > rv);
            b3 = (rintf((v.w + 1.0f) * 0.5f * 256.0f) > rv);
        }
        const uint32_t m0 = __ballot_sync(0xFFFFFFFFu, b0);
        const uint32_t m1 = __ballot_sync(0xFFFFFFFFu, b1);
        const uint32_t m2 = __ballot_sync(0xFFFFFFFFu, b2);
        const uint32_t m3 = __ballot_sync(0xFFFFFFFFu, b3);
        const uint64_t wa = (uint64_t)m0 | ((uint64_t)m1 << 32);
        const uint64_t wb = (uint64_t)m2 | ((uint64_t)m3 << 32);
        if (lane == 2 * it)     myword = wa;
        if (lane == 2 * it + 1) myword = wb;
        sig = sig * 0x9E3779B97F4A7C15ull + wa;
        sig = sig * 0x9E3779B97F4A7C15ull + wb;
    }

    sig *= 0xff51afd7ed558ccdULL;
    const uint32_t sig32 = (uint32_t)(sig ^ (sig >> 32));

    if (isX) {
        g_xbits[(size_t)row * WORDS + lane] = myword;
        if (lane == 0) g_xsig[row] = sig32;
    } else {
        g_pbits[(size_t)row * WORDS + lane] = myword;
        if (lane == 0) g_psig[row] = sig32;
    }

    // ---- lane 0: HT insert with collision detection (candidates only) ----
    if (lane == 0) {
        const unsigned long long entry =
            ((unsigned long long)sig32 << 32) | 0x80000000ull
          | ((unsigned long long)(isX ? 1 : 0) << 30) | (unsigned)row;
        uint32_t h = (sig32 * 2654435761u) & HT_MASK;
        while (true) {
            const unsigned long long prev = atomicCAS(&g_ht[h], 0ull, entry);
            if (prev == 0ull) break;                 // claimed empty slot
            if ((uint32_t)(prev >> 32) == sig32 &&
                (((prev >> 30) & 1ull) != (unsigned long long)(isX ? 1 : 0))) {
                const int oid = (int)(prev & 0x3FFFFFFFull);
                const int b = isX ? row : oid;
                const int o = isX ? oid : row;
                const uint32_t idx = atomicAdd(&g_cnt[b], 1u);
                if (idx < KCAP) g_olist[b][idx] = (uint32_t)o;
            }
            h = (h + 1) & HT_MASK;
        }
    }
}

// Exact verification: full 2048-bit compare of packed rows (k1 wrote them;
// the launch boundary orders the reads). Sig equality is never trusted alone.
__device__ __noinline__ bool fsu_full_cmp(int b, int o)
{
    const uint64_t* xb = &g_xbits[(size_t)b * WORDS];
    const uint64_t* pb = &g_pbits[(size_t)o * WORDS];
    #pragma unroll 8
    for (int k = 0; k < WORDS; ++k)
        if (__ldg(xb + k) != __ldg(pb + k)) return false;
    return true;
}

// -----------------------------------------------------------------------------
// Kernel 2: trivial finalize. 512 blocks x 256 threads. Each block: clears its
// 32 HT slots, checks the candidate counters of its 8 batch rows (typical: all
// zero -> done), verifies + applies any candidates, resets counters.
// out[] zeros were written by k1 (stream order), and only THIS kernel writes
// the 1.0 cells -> no store races anywhere.
// -----------------------------------------------------------------------------
__global__ __launch_bounds__(256) void fsu_fix_kernel(float* __restrict__ out)
{
    const int tid   = threadIdx.x;
    const int bbase = blockIdx.x * 8;

    // cleanup HT slice for next graph replay (512 x 32 = 16384)
    if (tid < 32) g_ht[blockIdx.x * 32 + tid] = 0ull;

    __shared__ uint32_t s_cnt[8];
    if (tid < 8) s_cnt[tid] = g_cnt[bbase + tid];
    __syncthreads();

    uint32_t any = 0;
    #pragma unroll
    for (int r = 0; r < 8; ++r) any |= s_cnt[r];
    if (any == 0) return;                            // typical path

    // rare path: verify + apply candidates for this block's rows
    for (int r = 0; r < 8; ++r) {
        const uint32_t n = s_cnt[r];
        if (n == 0) continue;
        const int b = bbase + r;
        if (n <= KCAP) {
            if (tid < (int)n) {
                const int o = (int)g_olist[b][tid];
                if (fsu_full_cmp(b, o))
                    out[(size_t)b * OUT_F + o] = 1.0f;
            }
        } else {
            // overflow (>KCAP sig-collisions on one row — effectively
            // impossible, but keeps exactness): rescan row b vs all psigs
            const uint32_t xs = __ldg(&g_xsig[b]);
            for (int o = tid; o < OUT_F; o += 256)
                if (__ldg(&g_psig[o]) == xs && fsu_full_cmp(b, o))
                    out[(size_t)b * OUT_F + o] = 1.0f;
        }
        if (tid == 0) g_cnt[b] = 0;                  // reset for next replay
    }
}

extern "C" void kernel_launch(void* const* d_in, const int* in_sizes, int n_in,
                              void* d_out, int out_size)
{
    const float* x   = (const float*)d_in[0];
    const float* w   = (const float*)d_in[1];
    const float* rng = (const float*)d_in[2];
    float* out = (float*)d_out;

    // (BATCH + OUT_F) warps = 8192 -> 1024 blocks of 8 warps; each block also
    // zero-fills 4096 float4 of the output.
    fsu_pack_zero_kernel<<<1024, 256>>>(x, w, rng,
                                        reinterpret_cast<float4*>(out));

    fsu_fix_kernel<<<BATCH / 8, 256>>>(out);         // 512 blocks, trivial
}

// round 17
// speedup vs baseline: 1.0615x; 1.0615x over previous
#include <cuda_runtime.h>
#include <stdint.h>

#define BATCH 4096
#define IN_F  2048
#define OUT_F 4096
#define WORDS (IN_F / 64)     // 32 u64 per row
#define RPB   8               // batch rows per match block

// Scratch (allocation-free: __device__ globals)
__device__ uint64_t g_xbits[(size_t)BATCH * WORDS];
__device__ uint64_t g_pbits[(size_t)OUT_F * WORDS];
__device__ uint32_t g_xsig[BATCH];
__device__ uint32_t g_psig[OUT_F];

// -----------------------------------------------------------------------------
// Kernel 1: fused pack + zero-fill (HBM-bound: 64 MB read + 64 MB write).
//   1024 blocks x 256 threads. Each block packs 8 rows (one warp per row)
//   AND zero-fills a 4096-float4 slice of the output.
//   Pack: float4 loads, 4 ballots/iter. Bit order within packed words is a
//   fixed permutation of element order, identical for x and path rows, so
//   packed-row equality <=> original-bit-row equality (exact).
//   Signature folded to 32 bits; every sig hit is exactly verified downstream.
// -----------------------------------------------------------------------------
__global__ __launch_bounds__(256) void fsu_pack_zero_kernel(
    const float* __restrict__ x,
    const float* __restrict__ w,
    const float* __restrict__ rng,
    float4* __restrict__ outv)
{
    // ---- zero-fill slice (pure store stream, overlaps with pack loads) ----
    {
        const float4 z = make_float4(0.0f, 0.0f, 0.0f, 0.0f);
        const int base = blockIdx.x * 4096;          // 4M float4 / 1024 blocks
        #pragma unroll
        for (int k = 0; k < 16; ++k)
            outv[base + k * 256 + threadIdx.x] = z;
    }

    // ---- pack 8 rows (one warp per row) ----
    const int gwarp = (blockIdx.x * blockDim.x + threadIdx.x) >> 5;
    const int lane  = threadIdx.x & 31;
    const bool isX  = gwarp < BATCH;
    const int row   = isX ? gwarp : (gwarp - BATCH);

    const float rv = __ldg(rng);
    const float4* src = reinterpret_cast<const float4*>(
        (isX ? (x + (size_t)row * IN_F) : (w + (size_t)row * IN_F)));

    uint64_t sig = 0;
    uint64_t myword = 0;

    #pragma unroll
    for (int it = 0; it < IN_F / 128; ++it) {        // 16 iterations
        const float4 v = __ldg(src + it * 32 + lane);
        bool b0, b1, b2, b3;
        if (isX) {
            b0 = (v.x > 0.5f); b1 = (v.y > 0.5f);
            b2 = (v.z > 0.5f); b3 = (v.w > 0.5f);
        } else {
            // BinGen/BSGen: prob=(w+1)*0.5; source=round(prob*256); bit = source > rng
            b0 = (rintf((v.x + 1.0f) * 0.5f * 256.0f) > rv);
            b1 = (rintf((v.y + 1.0f) * 0.5f * 256.0f) > rv);
            b2 = (rintf((v.z + 1.0f) * 0.5f * 256.0f) > rv);
            b3 = (rintf((v.w + 1.0f) * 0.5f * 256.0f) > rv);
        }
        const uint32_t m0 = __ballot_sync(0xFFFFFFFFu, b0);
        const uint32_t m1 = __ballot_sync(0xFFFFFFFFu, b1);
        const uint32_t m2 = __ballot_sync(0xFFFFFFFFu, b2);
        const uint32_t m3 = __ballot_sync(0xFFFFFFFFu, b3);
        const uint64_t wa = (uint64_t)m0 | ((uint64_t)m1 << 32);
        const uint64_t wb = (uint64_t)m2 | ((uint64_t)m3 << 32);
        if (lane == 2 * it)     myword = wa;
        if (lane == 2 * it + 1) myword = wb;
        sig = sig * 0x9E3779B97F4A7C15ull + wa;
        sig = sig * 0x9E3779B97F4A7C15ull + wb;
    }

    // fold to 32 bits (equal rows -> equal sig32; verification is exact anyway)
    sig *= 0xff51afd7ed558ccdULL;
    const uint32_t sig32 = (uint32_t)(sig ^ (sig >> 32));

    if (isX) {
        g_xbits[(size_t)row * WORDS + lane] = myword;
        if (lane == 0) g_xsig[row] = sig32;
    } else {
        g_pbits[(size_t)row * WORDS + lane] = myword;
        if (lane == 0) g_psig[row] = sig32;
    }
}

// Exact verification: full 2048-bit compare. Equal sigs alone is never
// trusted — collisions cannot produce wrong output.
__device__ __noinline__ bool fsu_full_cmp(int b, int o)
{
    const uint64_t* xb = &g_xbits[(size_t)b * WORDS];
    const uint64_t* pb = &g_pbits[(size_t)o * WORDS];
    #pragma unroll 8
    for (int k = 0; k < WORDS; ++k)
        if (__ldg(xb + k) != __ldg(pb + k)) return false;
    return true;
}

// -----------------------------------------------------------------------------
// Kernel 2: brute-force sig matrix compare, reshaped to the measured-fastest
// launch shape (512 x 256). Block owns RPB=8 batch rows (u32 sigs in regs);
// each thread reads 16 psigs as 4 uint4 (L2-resident 16 KB) and does 128
// independent register compares. Sig hits (expected ~0.004 chip-wide at 32
// bits over 16M pairs) are exactly verified before writing. out[] is already
// zeroed by kernel 1 (stream order).
// -----------------------------------------------------------------------------
__global__ __launch_bounds__(256) void fsu_match_kernel(float* __restrict__ out)
{
    const int tid   = threadIdx.x;
    const int bbase = blockIdx.x * RPB;

    uint32_t xs[RPB];
    #pragma unroll
    for (int r = 0; r < RPB; ++r)
        xs[r] = __ldg(&g_xsig[bbase + r]);

    const uint4* psv = reinterpret_cast<const uint4*>(g_psig);

    #pragma unroll
    for (int k = 0; k < OUT_F / (256 * 4); ++k) {    // 4 x uint4 per thread
        const int idx = k * 256 + tid;               // uint4 index
        const uint4 p = __ldg(&psv[idx]);
        const int o0 = idx * 4;
        #pragma unroll
        for (int r = 0; r < RPB; ++r) {
            const int b = bbase + r;
            if (p.x == xs[r] && fsu_full_cmp(b, o0 + 0))
                out[(size_t)b * OUT_F + o0 + 0] = 1.0f;
            if (p.y == xs[r] && fsu_full_cmp(b, o0 + 1))
                out[(size_t)b * OUT_F + o0 + 1] = 1.0f;
            if (p.z == xs[r] && fsu_full_cmp(b, o0 + 2))
                out[(size_t)b * OUT_F + o0 + 2] = 1.0f;
            if (p.w == xs[r] && fsu_full_cmp(b, o0 + 3))
                out[(size_t)b * OUT_F + o0 + 3] = 1.0f;
        }
    }
}

extern "C" void kernel_launch(void* const* d_in, const int* in_sizes, int n_in,
                              void* d_out, int out_size)
{
    const float* x   = (const float*)d_in[0];
    const float* w   = (const float*)d_in[1];
    const float* rng = (const float*)d_in[2];
    float* out = (float*)d_out;

    // (BATCH + OUT_F) warps = 8192 -> 1024 blocks of 8 warps; each block also
    // zero-fills 4096 float4 of the output.
    fsu_pack_zero_kernel<<<1024, 256>>>(x, w, rng,
                                        reinterpret_cast<float4*>(out));

    fsu_match_kernel<<<BATCH / RPB, 256>>>(out);     // 512 blocks
}